// round 4
// baseline (speedup 1.0000x reference)
#include <cuda_runtime.h>
#include <math.h>

// ---------------- problem constants ----------------
#define BATCH  2
#define SEQ    2048
#define DMODEL 2048
#define NHEAD  16
#define HDIM   128
#define FDIM   5504
#define MTOK   (BATCH*SEQ)      // 4096 token rows

// ---------------- device scratch (allocation-free rule: __device__ globals) ----------------
__device__ float g_xn  [MTOK*DMODEL];
__device__ float g_q   [MTOK*DMODEL];
__device__ float g_k   [MTOK*DMODEL];
__device__ float g_v   [MTOK*DMODEL];
__device__ float g_ctx [MTOK*DMODEL];
__device__ float g_h2  [MTOK*DMODEL];
__device__ float g_actg[MTOK*FDIM];
__device__ float g_actu[MTOK*FDIM];
__device__ float g_mask[MTOK];

// ---------------- RMSNorm: one block per row ----------------
__global__ __launch_bounds__(256) void rmsnorm_kernel(const float* __restrict__ x,
                                                      const float* __restrict__ w,
                                                      float* __restrict__ o)
{
    int row = blockIdx.x, tid = threadIdx.x;
    const float4* xr = (const float4*)(x + (size_t)row * DMODEL);
    float4 v0 = xr[tid];
    float4 v1 = xr[tid + 256];
    float ss = v0.x*v0.x + v0.y*v0.y + v0.z*v0.z + v0.w*v0.w
             + v1.x*v1.x + v1.y*v1.y + v1.z*v1.z + v1.w*v1.w;
    __shared__ float red[256];
    red[tid] = ss; __syncthreads();
    for (int off = 128; off > 0; off >>= 1) {
        if (tid < off) red[tid] += red[tid + off];
        __syncthreads();
    }
    float r = rsqrtf(red[0] * (1.0f / DMODEL) + 1e-6f);
    const float4* wr = (const float4*)w;
    float4 w0 = wr[tid], w1 = wr[tid + 256];
    float4* orow = (float4*)(o + (size_t)row * DMODEL);
    orow[tid]       = make_float4(v0.x*r*w0.x, v0.y*r*w0.y, v0.z*r*w0.z, v0.w*r*w0.w);
    orow[tid + 256] = make_float4(v1.x*r*w1.x, v1.y*r*w1.y, v1.z*r*w1.z, v1.w*r*w1.w);
}

// ---------------- GEMM: C[M,N] = A[M,K] @ W[N,K]^T  (+ epilogue variants) ----------------
// mode 0: C = acc + bias[n] (bias may be null)
// mode 1: C = acc + resid[m,n]
// mode 2: C += sel * acc, sel = (expert==0 ? mask[m] : 1-mask[m])
#define GBM 128
#define GBN 64
#define GBK 16
__global__ __launch_bounds__(256) void gemm_tn(const float* __restrict__ A,
                                               const float* __restrict__ W,
                                               const float* __restrict__ bias,
                                               const float* __restrict__ resid,
                                               const float* __restrict__ mask,
                                               float* __restrict__ C,
                                               int M, int N, int K, int mode, int expert)
{
    __shared__ float As[GBK][GBM];
    __shared__ float Ws[GBK][GBN];
    const int tid = threadIdx.x;
    const int tx = tid & 15, ty = tid >> 4;
    const int m0 = blockIdx.y * GBM, n0 = blockIdx.x * GBN;

    const int arow = tid >> 1, ak = (tid & 1) * 8;   // 128 rows x 16 k
    const int wrow = tid >> 2, wk = (tid & 3) * 4;   // 64 rows x 16 k
    const float* Ap = A + (size_t)(m0 + arow) * K + ak;
    const float* Wp = W + (size_t)(n0 + wrow) * K + wk;

    float acc[8][4];
    #pragma unroll
    for (int i = 0; i < 8; i++)
        #pragma unroll
        for (int j = 0; j < 4; j++) acc[i][j] = 0.f;

    for (int k0 = 0; k0 < K; k0 += GBK) {
        float4 a0 = *(const float4*)(Ap + k0);
        float4 a1 = *(const float4*)(Ap + k0 + 4);
        float4 w0 = *(const float4*)(Wp + k0);
        __syncthreads();
        As[ak+0][arow] = a0.x; As[ak+1][arow] = a0.y; As[ak+2][arow] = a0.z; As[ak+3][arow] = a0.w;
        As[ak+4][arow] = a1.x; As[ak+5][arow] = a1.y; As[ak+6][arow] = a1.z; As[ak+7][arow] = a1.w;
        Ws[wk+0][wrow] = w0.x; Ws[wk+1][wrow] = w0.y; Ws[wk+2][wrow] = w0.z; Ws[wk+3][wrow] = w0.w;
        __syncthreads();
        #pragma unroll
        for (int kk = 0; kk < GBK; kk++) {
            float4 av0 = *(const float4*)&As[kk][ty*8];
            float4 av1 = *(const float4*)&As[kk][ty*8 + 4];
            float4 wv  = *(const float4*)&Ws[kk][tx*4];
            float ar[8] = {av0.x, av0.y, av0.z, av0.w, av1.x, av1.y, av1.z, av1.w};
            float wr[4] = {wv.x, wv.y, wv.z, wv.w};
            #pragma unroll
            for (int i = 0; i < 8; i++)
                #pragma unroll
                for (int j = 0; j < 4; j++) acc[i][j] += ar[i] * wr[j];
        }
    }

    #pragma unroll
    for (int i = 0; i < 8; i++) {
        int m = m0 + ty*8 + i;
        size_t base = (size_t)m * N + n0 + tx*4;
        if (mode == 0) {
            #pragma unroll
            for (int j = 0; j < 4; j++)
                C[base + j] = acc[i][j] + (bias ? bias[n0 + tx*4 + j] : 0.f);
        } else if (mode == 1) {
            #pragma unroll
            for (int j = 0; j < 4; j++)
                C[base + j] = acc[i][j] + resid[base + j];
        } else {
            float sel = (expert == 0) ? mask[m] : (1.f - mask[m]);
            #pragma unroll
            for (int j = 0; j < 4; j++)
                C[base + j] += sel * acc[i][j];
        }
    }
}

// ---------------- RoPE (in-place on q and k) ----------------
__global__ __launch_bounds__(256) void rope_kernel(float* __restrict__ q, float* __restrict__ k)
{
    int t = blockIdx.x * 256 + threadIdx.x;       // [0, MTOK*NHEAD*64)
    int d = t & 63;
    int h = (t >> 6) & (NHEAD - 1);
    int row = t >> 10;                            // token row 0..4095
    float pos = (float)(row & (SEQ - 1));         // s = row % SEQ
    float invf = __powf(10000.f, -(float)d * (1.f / 64.f));
    float fr = pos * invf;
    float sn, cs;
    sincosf(fr, &sn, &cs);
    size_t base = (size_t)row * DMODEL + h * HDIM + d;
    float qlo = q[base], qhi = q[base + 64];
    q[base]      = qlo * cs - qhi * sn;
    q[base + 64] = qhi * cs + qlo * sn;
    float klo = k[base], khi = k[base + 64];
    k[base]      = klo * cs - khi * sn;
    k[base + 64] = khi * cs + klo * sn;
}

// ---------------- flash-style causal attention ----------------
// 64 q-rows per block; k-tiles of 64; K stored d-major in smem for conflict-free LDS.128.
#define QSS 132              // Q/V row stride (padded)
#define KTS 72               // K^T row stride (padded)
#define ATTN_SMEM_FLOATS (64*QSS + 128*KTS + 64*65 + 3*64)
#define ATTN_SMEM_BYTES  (ATTN_SMEM_FLOATS * 4)

__global__ __launch_bounds__(256) void attn_kernel(const float* __restrict__ q,
                                                   const float* __restrict__ k,
                                                   const float* __restrict__ v,
                                                   float* __restrict__ o)
{
    extern __shared__ float sm[];
    float* Qs = sm;                    // [64][QSS]
    float* KV = Qs + 64*QSS;           // K^T [128][KTS]  or V [64][QSS]
    float* Ps = KV + 128*KTS;          // [64][65]
    float* Ms = Ps + 64*65;
    float* Ls = Ms + 64;
    float* Al = Ls + 64;

    const int tid = threadIdx.x;
    const int tx = tid & 15, ty = tid >> 4;
    const int qt = blockIdx.x, h = blockIdx.y, b = blockIdx.z;
    const int qbase = qt * 64;
    const int ldr = tid >> 2, ldd = (tid & 3) * 32;

    { // load Q tile
        const float* src = q + (size_t)(b*SEQ + qbase + ldr) * DMODEL + h*HDIM + ldd;
        float* dst = Qs + ldr*QSS + ldd;
        #pragma unroll
        for (int u = 0; u < 8; u++) ((float4*)dst)[u] = ((const float4*)src)[u];
    }
    if (tid < 64) { Ms[tid] = -1e30f; Ls[tid] = 0.f; }

    float oa[4][8];
    #pragma unroll
    for (int i = 0; i < 4; i++)
        #pragma unroll
        for (int j = 0; j < 8; j++) oa[i][j] = 0.f;
    __syncthreads();

    for (int kt = 0; kt <= qt; kt++) {
        const int kbase = kt * 64;
        { // load K tile transposed: KV[d][col]
            const float* src = k + (size_t)(b*SEQ + kbase + ldr) * DMODEL + h*HDIM + ldd;
            #pragma unroll
            for (int u = 0; u < 8; u++) {
                float4 t4 = ((const float4*)src)[u];
                int d = ldd + u*4;
                KV[(d+0)*KTS + ldr] = t4.x;
                KV[(d+1)*KTS + ldr] = t4.y;
                KV[(d+2)*KTS + ldr] = t4.z;
                KV[(d+3)*KTS + ldr] = t4.w;
            }
        }
        __syncthreads();

        // S = Q K^T  (4x4 per thread)
        float s[4][4];
        #pragma unroll
        for (int i = 0; i < 4; i++)
            #pragma unroll
            for (int j = 0; j < 4; j++) s[i][j] = 0.f;
        #pragma unroll 4
        for (int d = 0; d < HDIM; d++) {
            float qv[4];
            #pragma unroll
            for (int i = 0; i < 4; i++) qv[i] = Qs[(ty*4+i)*QSS + d];
            float4 kv = *(const float4*)&KV[d*KTS + tx*4];
            #pragma unroll
            for (int i = 0; i < 4; i++) {
                s[i][0] += qv[i]*kv.x; s[i][1] += qv[i]*kv.y;
                s[i][2] += qv[i]*kv.z; s[i][3] += qv[i]*kv.w;
            }
        }
        const float scale = 0.08838834764831845f;  // 1/sqrt(128)
        #pragma unroll
        for (int i = 0; i < 4; i++)
            #pragma unroll
            for (int j = 0; j < 4; j++) {
                int qg = qbase + ty*4 + i, kg = kbase + tx*4 + j;
                float val = s[i][j] * scale;
                if (kg > qg) val = -1e30f;
                Ps[(ty*4+i)*65 + tx*4 + j] = val;
            }
        __syncthreads();

        // online softmax, one thread per row
        if (tid < 64) {
            float mold = Ms[tid], mx = mold;
            float* pr = Ps + tid*65;
            #pragma unroll 8
            for (int j = 0; j < 64; j++) mx = fmaxf(mx, pr[j]);
            float sum = 0.f;
            #pragma unroll 8
            for (int j = 0; j < 64; j++) { float e = __expf(pr[j] - mx); pr[j] = e; sum += e; }
            float al = __expf(mold - mx);
            Ls[tid] = Ls[tid]*al + sum;
            Ms[tid] = mx;
            Al[tid] = al;
        }
        __syncthreads();

        { // load V tile row-major over KV
            const float* src = v + (size_t)(b*SEQ + kbase + ldr) * DMODEL + h*HDIM + ldd;
            float* dst = KV + ldr*QSS + ldd;
            #pragma unroll
            for (int u = 0; u < 8; u++) ((float4*)dst)[u] = ((const float4*)src)[u];
        }
        float al[4];
        #pragma unroll
        for (int i = 0; i < 4; i++) al[i] = Al[ty*4 + i];
        #pragma unroll
        for (int i = 0; i < 4; i++)
            #pragma unroll
            for (int j = 0; j < 8; j++) oa[i][j] *= al[i];
        __syncthreads();

        // O += P V
        #pragma unroll 2
        for (int kk = 0; kk < 64; kk++) {
            float p[4];
            #pragma unroll
            for (int i = 0; i < 4; i++) p[i] = Ps[(ty*4+i)*65 + kk];
            float4 v0 = *(const float4*)&KV[kk*QSS + tx*8];
            float4 v1 = *(const float4*)&KV[kk*QSS + tx*8 + 4];
            #pragma unroll
            for (int i = 0; i < 4; i++) {
                oa[i][0] += p[i]*v0.x; oa[i][1] += p[i]*v0.y;
                oa[i][2] += p[i]*v0.z; oa[i][3] += p[i]*v0.w;
                oa[i][4] += p[i]*v1.x; oa[i][5] += p[i]*v1.y;
                oa[i][6] += p[i]*v1.z; oa[i][7] += p[i]*v1.w;
            }
        }
        __syncthreads();
    }

    #pragma unroll
    for (int i = 0; i < 4; i++) {
        float li = 1.f / Ls[ty*4 + i];
        size_t base = (size_t)(b*SEQ + qbase + ty*4 + i) * DMODEL + h*HDIM + tx*8;
        #pragma unroll
        for (int j = 0; j < 8; j++) o[base + j] = oa[i][j] * li;
    }
}

// ---------------- router: top-1 over 2 experts ----------------
__global__ __launch_bounds__(128) void router_kernel(const float* __restrict__ xn,
                                                     const float* __restrict__ rw,
                                                     const float* __restrict__ rb,
                                                     float* __restrict__ mask)
{
    int row = blockIdx.x, tid = threadIdx.x;
    float a0 = 0.f, a1 = 0.f;
    const float* xr = xn + (size_t)row * DMODEL;
    for (int d = tid; d < DMODEL; d += 128) {
        float x = xr[d];
        a0 += x * rw[d];
        a1 += x * rw[DMODEL + d];
    }
    __shared__ float s0[128], s1[128];
    s0[tid] = a0; s1[tid] = a1; __syncthreads();
    for (int off = 64; off > 0; off >>= 1) {
        if (tid < off) { s0[tid] += s0[tid + off]; s1[tid] += s1[tid + off]; }
        __syncthreads();
    }
    if (tid == 0)
        mask[row] = (s0[0] + rb[0] >= s1[0] + rb[1]) ? 1.f : 0.f;
}

// ---------------- SiLU(gate) * up ----------------
__global__ __launch_bounds__(256) void silu_mul_kernel(const float4* __restrict__ g,
                                                       const float4* __restrict__ u,
                                                       float4* __restrict__ o, int n4)
{
    int i = blockIdx.x * 256 + threadIdx.x;
    if (i >= n4) return;
    float4 a = g[i], b = u[i], r;
    r.x = a.x / (1.f + __expf(-a.x)) * b.x;
    r.y = a.y / (1.f + __expf(-a.y)) * b.y;
    r.z = a.z / (1.f + __expf(-a.z)) * b.z;
    r.w = a.w / (1.f + __expf(-a.w)) * b.w;
    o[i] = r;
}

// ---------------- launch ----------------
extern "C" void kernel_launch(void* const* d_in, const int* in_sizes, int n_in,
                              void* d_out, int out_size)
{
    const float* hidden = (const float*)d_in[0];
    const float* ln1w   = (const float*)d_in[1];
    const float* wq     = (const float*)d_in[2];
    const float* bq     = (const float*)d_in[3];
    const float* wk     = (const float*)d_in[4];
    const float* bk     = (const float*)d_in[5];
    const float* wv     = (const float*)d_in[6];
    const float* bv     = (const float*)d_in[7];
    const float* wo     = (const float*)d_in[8];
    const float* ln2w   = (const float*)d_in[9];
    const float* e1g    = (const float*)d_in[10];
    const float* e1u    = (const float*)d_in[11];
    const float* e1d    = (const float*)d_in[12];
    const float* e2g    = (const float*)d_in[13];
    const float* e2u    = (const float*)d_in[14];
    const float* e2d    = (const float*)d_in[15];
    const float* rw     = (const float*)d_in[16];
    const float* rb     = (const float*)d_in[17];
    float* out = (float*)d_out;

    void* p;
    cudaGetSymbolAddress(&p, g_xn);   float* xn   = (float*)p;
    cudaGetSymbolAddress(&p, g_q);    float* q    = (float*)p;
    cudaGetSymbolAddress(&p, g_k);    float* k    = (float*)p;
    cudaGetSymbolAddress(&p, g_v);    float* v    = (float*)p;
    cudaGetSymbolAddress(&p, g_ctx);  float* ctx  = (float*)p;
    cudaGetSymbolAddress(&p, g_h2);   float* h2   = (float*)p;
    cudaGetSymbolAddress(&p, g_actg); float* actg = (float*)p;
    cudaGetSymbolAddress(&p, g_actu); float* actu = (float*)p;
    cudaGetSymbolAddress(&p, g_mask); float* mask = (float*)p;

    // 1. pre-attention norm
    rmsnorm_kernel<<<MTOK, 256>>>(hidden, ln1w, xn);

    // 2. QKV projections
    dim3 gD(DMODEL/GBN, MTOK/GBM);
    gemm_tn<<<gD, 256>>>(xn, wq, bq, nullptr, nullptr, q, MTOK, DMODEL, DMODEL, 0, 0);
    gemm_tn<<<gD, 256>>>(xn, wk, bk, nullptr, nullptr, k, MTOK, DMODEL, DMODEL, 0, 0);
    gemm_tn<<<gD, 256>>>(xn, wv, bv, nullptr, nullptr, v, MTOK, DMODEL, DMODEL, 0, 0);

    // 3. RoPE
    rope_kernel<<<(MTOK*NHEAD*64)/256, 256>>>(q, k);

    // 4. causal attention
    cudaFuncSetAttribute(attn_kernel, cudaFuncAttributeMaxDynamicSharedMemorySize, ATTN_SMEM_BYTES);
    attn_kernel<<<dim3(SEQ/64, NHEAD, BATCH), 256, ATTN_SMEM_BYTES>>>(q, k, v, ctx);

    // 5. O projection + residual
    gemm_tn<<<gD, 256>>>(ctx, wo, nullptr, hidden, nullptr, h2, MTOK, DMODEL, DMODEL, 1, 0);

    // 6. post-attention norm + router
    rmsnorm_kernel<<<MTOK, 256>>>(h2, ln2w, xn);
    router_kernel<<<MTOK, 128>>>(xn, rw, rb, mask);

    // 7. residual into output
    cudaMemcpyAsync(out, h2, (size_t)MTOK * DMODEL * sizeof(float),
                    cudaMemcpyDeviceToDevice, 0);

    // 8. expert 1
    dim3 gF(FDIM/GBN, MTOK/GBM);
    gemm_tn<<<gF, 256>>>(xn, e1g, nullptr, nullptr, nullptr, actg, MTOK, FDIM, DMODEL, 0, 0);
    gemm_tn<<<gF, 256>>>(xn, e1u, nullptr, nullptr, nullptr, actu, MTOK, FDIM, DMODEL, 0, 0);
    silu_mul_kernel<<<(MTOK*FDIM/4 + 255)/256, 256>>>((const float4*)actg, (const float4*)actu,
                                                      (float4*)actg, MTOK*FDIM/4);
    gemm_tn<<<gD, 256>>>(actg, e1d, nullptr, nullptr, mask, out, MTOK, DMODEL, FDIM, 2, 0);

    // 9. expert 2
    gemm_tn<<<gF, 256>>>(xn, e2g, nullptr, nullptr, nullptr, actg, MTOK, FDIM, DMODEL, 0, 0);
    gemm_tn<<<gF, 256>>>(xn, e2u, nullptr, nullptr, nullptr, actu, MTOK, FDIM, DMODEL, 0, 0);
    silu_mul_kernel<<<(MTOK*FDIM/4 + 255)/256, 256>>>((const float4*)actg, (const float4*)actu,
                                                      (float4*)actg, MTOK*FDIM/4);
    gemm_tn<<<gD, 256>>>(actg, e2d, nullptr, nullptr, mask, out, MTOK, DMODEL, FDIM, 2, 1);
}

// round 5
// speedup vs baseline: 1.9312x; 1.9312x over previous
#include <cuda_runtime.h>
#include <stdint.h>
#include <math.h>

// ---------------- problem constants ----------------
#define BATCH  2
#define SEQ    2048
#define DMODEL 2048
#define NHEAD  16
#define HDIM   128
#define FDIM   5504
#define MTOK   (BATCH*SEQ)      // 4096 token rows

// ---------------- device scratch ----------------
__device__ float g_xn  [MTOK*DMODEL];
__device__ float g_q   [MTOK*DMODEL];
__device__ float g_k   [MTOK*DMODEL];
__device__ float g_v   [MTOK*DMODEL];
__device__ float g_ctx [MTOK*DMODEL];
__device__ float g_h2  [MTOK*DMODEL];
__device__ float g_actg[MTOK*FDIM];
__device__ float g_actu[MTOK*FDIM];
__device__ float g_mask[MTOK];

// ---------------- RMSNorm ----------------
__global__ __launch_bounds__(256) void rmsnorm_kernel(const float* __restrict__ x,
                                                      const float* __restrict__ w,
                                                      float* __restrict__ o)
{
    int row = blockIdx.x, tid = threadIdx.x;
    const float4* xr = (const float4*)(x + (size_t)row * DMODEL);
    float4 v0 = xr[tid];
    float4 v1 = xr[tid + 256];
    float ss = v0.x*v0.x + v0.y*v0.y + v0.z*v0.z + v0.w*v0.w
             + v1.x*v1.x + v1.y*v1.y + v1.z*v1.z + v1.w*v1.w;
    __shared__ float red[256];
    red[tid] = ss; __syncthreads();
    for (int off = 128; off > 0; off >>= 1) {
        if (tid < off) red[tid] += red[tid + off];
        __syncthreads();
    }
    float r = rsqrtf(red[0] * (1.0f / DMODEL) + 1e-6f);
    const float4* wr = (const float4*)w;
    float4 w0 = wr[tid], w1 = wr[tid + 256];
    float4* orow = (float4*)(o + (size_t)row * DMODEL);
    orow[tid]       = make_float4(v0.x*r*w0.x, v0.y*r*w0.y, v0.z*r*w0.z, v0.w*r*w0.w);
    orow[tid + 256] = make_float4(v1.x*r*w1.x, v1.y*r*w1.y, v1.z*r*w1.z, v1.w*r*w1.w);
}

// ---------------- tf32 tensor-core GEMM: C[M,N] = A[M,K] @ W[N,K]^T ----------------
// mode 0: C = acc + bias[n] (bias may be null)
// mode 1: C = acc + resid[m,n]
// mode 2: C += sel * acc, sel = (expert==0 ? mask[m] : 1-mask[m])
#define TBM 128
#define TBN 128
#define TBK 32
#define SST 36                   // smem row stride (floats) -> conflict-free frags
#define STAGE_F (128*SST)        // 4608 floats per stage per operand
#define GEMM_SMEM_BYTES (4*STAGE_F*4)   // 2 operands x 2 stages

__device__ __forceinline__ void cp16(uint32_t dst, const void* src) {
    asm volatile("cp.async.cg.shared.global [%0], [%1], 16;\n" :: "r"(dst), "l"(src));
}
__device__ __forceinline__ uint32_t f2tf32(float x) {
    uint32_t r;
    asm("cvt.rna.tf32.f32 %0, %1;\n" : "=r"(r) : "f"(x));
    return r;
}
__device__ __forceinline__ void mma_tf32(float* c, const uint32_t* a, const uint32_t* b) {
    asm volatile(
        "mma.sync.aligned.m16n8k8.row.col.f32.tf32.tf32.f32 "
        "{%0,%1,%2,%3}, {%4,%5,%6,%7}, {%8,%9}, {%0,%1,%2,%3};\n"
        : "+f"(c[0]), "+f"(c[1]), "+f"(c[2]), "+f"(c[3])
        : "r"(a[0]), "r"(a[1]), "r"(a[2]), "r"(a[3]), "r"(b[0]), "r"(b[1]));
}

__global__ __launch_bounds__(256) void gemm_tf32(const float* __restrict__ A,
                                                 const float* __restrict__ W,
                                                 const float* __restrict__ bias,
                                                 const float* __restrict__ resid,
                                                 const float* __restrict__ mask,
                                                 float* __restrict__ C,
                                                 int M, int N, int K, int mode, int expert)
{
    extern __shared__ float sm[];
    float* As = sm;                    // [2][STAGE_F]
    float* Ws = sm + 2*STAGE_F;        // [2][STAGE_F]

    const int tid = threadIdx.x;
    const int m0 = blockIdx.y * TBM, n0 = blockIdx.x * TBN;

    // loaders: 128 rows x 32 k per operand; thread -> row tid/2, 16-float half (tid&1)
    const int lrow = tid >> 1, lcol = (tid & 1) * 16;
    const float* Ag = A + (size_t)(m0 + lrow) * K + lcol;
    const float* Wg = W + (size_t)(n0 + lrow) * K + lcol;
    uint32_t aBase = (uint32_t)__cvta_generic_to_shared(As + lrow*SST + lcol);
    uint32_t wBase = (uint32_t)__cvta_generic_to_shared(Ws + lrow*SST + lcol);

    const int wid = tid >> 5, lane = tid & 31;
    const int g = lane >> 2, cq = lane & 3;
    const int wm = (wid & 1) * 64;     // warp tile 64x32
    const int wn = (wid >> 1) * 32;

    float acc[4][4][4];
    #pragma unroll
    for (int mt = 0; mt < 4; mt++)
        #pragma unroll
        for (int nt = 0; nt < 4; nt++)
            #pragma unroll
            for (int i = 0; i < 4; i++) acc[mt][nt][i] = 0.f;

    const int ktiles = K / TBK;

    // prefetch stage 0
    #pragma unroll
    for (int u = 0; u < 4; u++) {
        cp16(aBase + u*16, Ag + u*4);
        cp16(wBase + u*16, Wg + u*4);
    }
    asm volatile("cp.async.commit_group;\n");

    int buf = 0;
    for (int kt = 0; kt < ktiles; kt++) {
        if (kt + 1 < ktiles) {
            const float* ag = Ag + (size_t)(kt+1) * TBK;
            const float* wg = Wg + (size_t)(kt+1) * TBK;
            uint32_t ab = aBase + (uint32_t)(buf^1) * STAGE_F * 4;
            uint32_t wb = wBase + (uint32_t)(buf^1) * STAGE_F * 4;
            #pragma unroll
            for (int u = 0; u < 4; u++) {
                cp16(ab + u*16, ag + u*4);
                cp16(wb + u*16, wg + u*4);
            }
        }
        asm volatile("cp.async.commit_group;\n");
        asm volatile("cp.async.wait_group 1;\n");
        __syncthreads();

        const float* Ab = As + buf*STAGE_F;
        const float* Wb = Ws + buf*STAGE_F;
        #pragma unroll
        for (int ks = 0; ks < 4; ks++) {
            const int kk = ks * 8;
            uint32_t a[4][4], b[4][2];
            #pragma unroll
            for (int mt = 0; mt < 4; mt++) {
                const float* p = Ab + (wm + mt*16 + g)*SST + kk + cq;
                a[mt][0] = f2tf32(p[0]);
                a[mt][1] = f2tf32(p[8*SST]);
                a[mt][2] = f2tf32(p[4]);
                a[mt][3] = f2tf32(p[8*SST + 4]);
            }
            #pragma unroll
            for (int nt = 0; nt < 4; nt++) {
                const float* p = Wb + (wn + nt*8 + g)*SST + kk + cq;
                b[nt][0] = f2tf32(p[0]);
                b[nt][1] = f2tf32(p[4]);
            }
            #pragma unroll
            for (int mt = 0; mt < 4; mt++)
                #pragma unroll
                for (int nt = 0; nt < 4; nt++)
                    mma_tf32(acc[mt][nt], a[mt], b[nt]);
        }
        __syncthreads();
        buf ^= 1;
    }

    // epilogue
    #pragma unroll
    for (int mt = 0; mt < 4; mt++) {
        const int r0 = m0 + wm + mt*16 + g;
        #pragma unroll
        for (int nt = 0; nt < 4; nt++) {
            const int cc = n0 + wn + nt*8 + cq*2;
            const float* c = acc[mt][nt];
            size_t i0 = (size_t)r0 * N + cc;
            size_t i1 = (size_t)(r0 + 8) * N + cc;
            if (mode == 0) {
                float b0 = bias ? bias[cc] : 0.f;
                float b1 = bias ? bias[cc+1] : 0.f;
                C[i0] = c[0] + b0;  C[i0+1] = c[1] + b1;
                C[i1] = c[2] + b0;  C[i1+1] = c[3] + b1;
            } else if (mode == 1) {
                C[i0] = c[0] + resid[i0];  C[i0+1] = c[1] + resid[i0+1];
                C[i1] = c[2] + resid[i1];  C[i1+1] = c[3] + resid[i1+1];
            } else {
                float s0 = (expert == 0) ? mask[r0]   : (1.f - mask[r0]);
                float s1 = (expert == 0) ? mask[r0+8] : (1.f - mask[r0+8]);
                C[i0] += s0*c[0];  C[i0+1] += s0*c[1];
                C[i1] += s1*c[2];  C[i1+1] += s1*c[3];
            }
        }
    }
}

// ---------------- RoPE (in-place on q and k) ----------------
__global__ __launch_bounds__(256) void rope_kernel(float* __restrict__ q, float* __restrict__ k)
{
    int t = blockIdx.x * 256 + threadIdx.x;
    int d = t & 63;
    int h = (t >> 6) & (NHEAD - 1);
    int row = t >> 10;
    float pos = (float)(row & (SEQ - 1));
    float invf = __powf(10000.f, -(float)d * (1.f / 64.f));
    float fr = pos * invf;
    float sn, cs;
    sincosf(fr, &sn, &cs);
    size_t base = (size_t)row * DMODEL + h * HDIM + d;
    float qlo = q[base], qhi = q[base + 64];
    q[base]      = qlo * cs - qhi * sn;
    q[base + 64] = qhi * cs + qlo * sn;
    float klo = k[base], khi = k[base + 64];
    k[base]      = klo * cs - khi * sn;
    k[base + 64] = khi * cs + klo * sn;
}

// ---------------- flash-style causal attention ----------------
#define QSS 132
#define KTS 72
#define ATTN_SMEM_FLOATS (64*QSS + 128*KTS + 64*65 + 3*64)
#define ATTN_SMEM_BYTES  (ATTN_SMEM_FLOATS * 4)

__global__ __launch_bounds__(256) void attn_kernel(const float* __restrict__ q,
                                                   const float* __restrict__ k,
                                                   const float* __restrict__ v,
                                                   float* __restrict__ o)
{
    extern __shared__ float sm[];
    float* Qs = sm;
    float* KV = Qs + 64*QSS;
    float* Ps = KV + 128*KTS;
    float* Ms = Ps + 64*65;
    float* Ls = Ms + 64;
    float* Al = Ls + 64;

    const int tid = threadIdx.x;
    const int tx = tid & 15, ty = tid >> 4;
    const int qt = blockIdx.x, h = blockIdx.y, b = blockIdx.z;
    const int qbase = qt * 64;
    const int ldr = tid >> 2, ldd = (tid & 3) * 32;

    {
        const float* src = q + (size_t)(b*SEQ + qbase + ldr) * DMODEL + h*HDIM + ldd;
        float* dst = Qs + ldr*QSS + ldd;
        #pragma unroll
        for (int u = 0; u < 8; u++) ((float4*)dst)[u] = ((const float4*)src)[u];
    }
    if (tid < 64) { Ms[tid] = -1e30f; Ls[tid] = 0.f; }

    float oa[4][8];
    #pragma unroll
    for (int i = 0; i < 4; i++)
        #pragma unroll
        for (int j = 0; j < 8; j++) oa[i][j] = 0.f;
    __syncthreads();

    for (int kt = 0; kt <= qt; kt++) {
        const int kbase = kt * 64;
        {
            const float* src = k + (size_t)(b*SEQ + kbase + ldr) * DMODEL + h*HDIM + ldd;
            #pragma unroll
            for (int u = 0; u < 8; u++) {
                float4 t4 = ((const float4*)src)[u];
                int d = ldd + u*4;
                KV[(d+0)*KTS + ldr] = t4.x;
                KV[(d+1)*KTS + ldr] = t4.y;
                KV[(d+2)*KTS + ldr] = t4.z;
                KV[(d+3)*KTS + ldr] = t4.w;
            }
        }
        __syncthreads();

        float s[4][4];
        #pragma unroll
        for (int i = 0; i < 4; i++)
            #pragma unroll
            for (int j = 0; j < 4; j++) s[i][j] = 0.f;
        #pragma unroll 4
        for (int d = 0; d < HDIM; d++) {
            float qv[4];
            #pragma unroll
            for (int i = 0; i < 4; i++) qv[i] = Qs[(ty*4+i)*QSS + d];
            float4 kv = *(const float4*)&KV[d*KTS + tx*4];
            #pragma unroll
            for (int i = 0; i < 4; i++) {
                s[i][0] += qv[i]*kv.x; s[i][1] += qv[i]*kv.y;
                s[i][2] += qv[i]*kv.z; s[i][3] += qv[i]*kv.w;
            }
        }
        const float scale = 0.08838834764831845f;
        #pragma unroll
        for (int i = 0; i < 4; i++)
            #pragma unroll
            for (int j = 0; j < 4; j++) {
                int qg = qbase + ty*4 + i, kg = kbase + tx*4 + j;
                float val = s[i][j] * scale;
                if (kg > qg) val = -1e30f;
                Ps[(ty*4+i)*65 + tx*4 + j] = val;
            }
        __syncthreads();

        if (tid < 64) {
            float mold = Ms[tid], mx = mold;
            float* pr = Ps + tid*65;
            #pragma unroll 8
            for (int j = 0; j < 64; j++) mx = fmaxf(mx, pr[j]);
            float sum = 0.f;
            #pragma unroll 8
            for (int j = 0; j < 64; j++) { float e = __expf(pr[j] - mx); pr[j] = e; sum += e; }
            float al = __expf(mold - mx);
            Ls[tid] = Ls[tid]*al + sum;
            Ms[tid] = mx;
            Al[tid] = al;
        }
        __syncthreads();

        {
            const float* src = v + (size_t)(b*SEQ + kbase + ldr) * DMODEL + h*HDIM + ldd;
            float* dst = KV + ldr*QSS + ldd;
            #pragma unroll
            for (int u = 0; u < 8; u++) ((float4*)dst)[u] = ((const float4*)src)[u];
        }
        float al[4];
        #pragma unroll
        for (int i = 0; i < 4; i++) al[i] = Al[ty*4 + i];
        #pragma unroll
        for (int i = 0; i < 4; i++)
            #pragma unroll
            for (int j = 0; j < 8; j++) oa[i][j] *= al[i];
        __syncthreads();

        #pragma unroll 2
        for (int kk = 0; kk < 64; kk++) {
            float p[4];
            #pragma unroll
            for (int i = 0; i < 4; i++) p[i] = Ps[(ty*4+i)*65 + kk];
            float4 v0 = *(const float4*)&KV[kk*QSS + tx*8];
            float4 v1 = *(const float4*)&KV[kk*QSS + tx*8 + 4];
            #pragma unroll
            for (int i = 0; i < 4; i++) {
                oa[i][0] += p[i]*v0.x; oa[i][1] += p[i]*v0.y;
                oa[i][2] += p[i]*v0.z; oa[i][3] += p[i]*v0.w;
                oa[i][4] += p[i]*v1.x; oa[i][5] += p[i]*v1.y;
                oa[i][6] += p[i]*v1.z; oa[i][7] += p[i]*v1.w;
            }
        }
        __syncthreads();
    }

    #pragma unroll
    for (int i = 0; i < 4; i++) {
        float li = 1.f / Ls[ty*4 + i];
        size_t base = (size_t)(b*SEQ + qbase + ty*4 + i) * DMODEL + h*HDIM + tx*8;
        #pragma unroll
        for (int j = 0; j < 8; j++) o[base + j] = oa[i][j] * li;
    }
}

// ---------------- router ----------------
__global__ __launch_bounds__(128) void router_kernel(const float* __restrict__ xn,
                                                     const float* __restrict__ rw,
                                                     const float* __restrict__ rb,
                                                     float* __restrict__ mask)
{
    int row = blockIdx.x, tid = threadIdx.x;
    float a0 = 0.f, a1 = 0.f;
    const float* xr = xn + (size_t)row * DMODEL;
    for (int d = tid; d < DMODEL; d += 128) {
        float x = xr[d];
        a0 += x * rw[d];
        a1 += x * rw[DMODEL + d];
    }
    __shared__ float s0[128], s1[128];
    s0[tid] = a0; s1[tid] = a1; __syncthreads();
    for (int off = 64; off > 0; off >>= 1) {
        if (tid < off) { s0[tid] += s0[tid + off]; s1[tid] += s1[tid + off]; }
        __syncthreads();
    }
    if (tid == 0)
        mask[row] = (s0[0] + rb[0] >= s1[0] + rb[1]) ? 1.f : 0.f;
}

// ---------------- SiLU(gate) * up ----------------
__global__ __launch_bounds__(256) void silu_mul_kernel(const float4* __restrict__ g,
                                                       const float4* __restrict__ u,
                                                       float4* __restrict__ o, int n4)
{
    int i = blockIdx.x * 256 + threadIdx.x;
    if (i >= n4) return;
    float4 a = g[i], b = u[i], r;
    r.x = a.x / (1.f + __expf(-a.x)) * b.x;
    r.y = a.y / (1.f + __expf(-a.y)) * b.y;
    r.z = a.z / (1.f + __expf(-a.z)) * b.z;
    r.w = a.w / (1.f + __expf(-a.w)) * b.w;
    o[i] = r;
}

// ---------------- launch ----------------
extern "C" void kernel_launch(void* const* d_in, const int* in_sizes, int n_in,
                              void* d_out, int out_size)
{
    const float* hidden = (const float*)d_in[0];
    const float* ln1w   = (const float*)d_in[1];
    const float* wq     = (const float*)d_in[2];
    const float* bq     = (const float*)d_in[3];
    const float* wk     = (const float*)d_in[4];
    const float* bk     = (const float*)d_in[5];
    const float* wv     = (const float*)d_in[6];
    const float* bv     = (const float*)d_in[7];
    const float* wo     = (const float*)d_in[8];
    const float* ln2w   = (const float*)d_in[9];
    const float* e1g    = (const float*)d_in[10];
    const float* e1u    = (const float*)d_in[11];
    const float* e1d    = (const float*)d_in[12];
    const float* e2g    = (const float*)d_in[13];
    const float* e2u    = (const float*)d_in[14];
    const float* e2d    = (const float*)d_in[15];
    const float* rw     = (const float*)d_in[16];
    const float* rb     = (const float*)d_in[17];
    float* out = (float*)d_out;

    void* p;
    cudaGetSymbolAddress(&p, g_xn);   float* xn   = (float*)p;
    cudaGetSymbolAddress(&p, g_q);    float* q    = (float*)p;
    cudaGetSymbolAddress(&p, g_k);    float* k    = (float*)p;
    cudaGetSymbolAddress(&p, g_v);    float* v    = (float*)p;
    cudaGetSymbolAddress(&p, g_ctx);  float* ctx  = (float*)p;
    cudaGetSymbolAddress(&p, g_h2);   float* h2   = (float*)p;
    cudaGetSymbolAddress(&p, g_actg); float* actg = (float*)p;
    cudaGetSymbolAddress(&p, g_actu); float* actu = (float*)p;
    cudaGetSymbolAddress(&p, g_mask); float* mask = (float*)p;

    cudaFuncSetAttribute(gemm_tf32, cudaFuncAttributeMaxDynamicSharedMemorySize, GEMM_SMEM_BYTES);
    cudaFuncSetAttribute(attn_kernel, cudaFuncAttributeMaxDynamicSharedMemorySize, ATTN_SMEM_BYTES);

    // 1. pre-attention norm
    rmsnorm_kernel<<<MTOK, 256>>>(hidden, ln1w, xn);

    // 2. QKV projections
    dim3 gD(DMODEL/TBN, MTOK/TBM);
    gemm_tf32<<<gD, 256, GEMM_SMEM_BYTES>>>(xn, wq, bq, nullptr, nullptr, q, MTOK, DMODEL, DMODEL, 0, 0);
    gemm_tf32<<<gD, 256, GEMM_SMEM_BYTES>>>(xn, wk, bk, nullptr, nullptr, k, MTOK, DMODEL, DMODEL, 0, 0);
    gemm_tf32<<<gD, 256, GEMM_SMEM_BYTES>>>(xn, wv, bv, nullptr, nullptr, v, MTOK, DMODEL, DMODEL, 0, 0);

    // 3. RoPE
    rope_kernel<<<(MTOK*NHEAD*64)/256, 256>>>(q, k);

    // 4. causal attention
    attn_kernel<<<dim3(SEQ/64, NHEAD, BATCH), 256, ATTN_SMEM_BYTES>>>(q, k, v, ctx);

    // 5. O projection + residual
    gemm_tf32<<<gD, 256, GEMM_SMEM_BYTES>>>(ctx, wo, nullptr, hidden, nullptr, h2, MTOK, DMODEL, DMODEL, 1, 0);

    // 6. post-attention norm + router
    rmsnorm_kernel<<<MTOK, 256>>>(h2, ln2w, xn);
    router_kernel<<<MTOK, 128>>>(xn, rw, rb, mask);

    // 7. residual into output
    cudaMemcpyAsync(out, h2, (size_t)MTOK * DMODEL * sizeof(float),
                    cudaMemcpyDeviceToDevice, 0);

    // 8. expert 1
    dim3 gF(FDIM/TBN, MTOK/TBM);
    gemm_tf32<<<gF, 256, GEMM_SMEM_BYTES>>>(xn, e1g, nullptr, nullptr, nullptr, actg, MTOK, FDIM, DMODEL, 0, 0);
    gemm_tf32<<<gF, 256, GEMM_SMEM_BYTES>>>(xn, e1u, nullptr, nullptr, nullptr, actu, MTOK, FDIM, DMODEL, 0, 0);
    silu_mul_kernel<<<(MTOK*FDIM/4 + 255)/256, 256>>>((const float4*)actg, (const float4*)actu,
                                                      (float4*)actg, MTOK*FDIM/4);
    gemm_tf32<<<gD, 256, GEMM_SMEM_BYTES>>>(actg, e1d, nullptr, nullptr, mask, out, MTOK, DMODEL, FDIM, 2, 0);

    // 9. expert 2
    gemm_tf32<<<gF, 256, GEMM_SMEM_BYTES>>>(xn, e2g, nullptr, nullptr, nullptr, actg, MTOK, FDIM, DMODEL, 0, 0);
    gemm_tf32<<<gF, 256, GEMM_SMEM_BYTES>>>(xn, e2u, nullptr, nullptr, nullptr, actu, MTOK, FDIM, DMODEL, 0, 0);
    silu_mul_kernel<<<(MTOK*FDIM/4 + 255)/256, 256>>>((const float4*)actg, (const float4*)actu,
                                                      (float4*)actg, MTOK*FDIM/4);
    gemm_tf32<<<gD, 256, GEMM_SMEM_BYTES>>>(actg, e2d, nullptr, nullptr, mask, out, MTOK, DMODEL, FDIM, 2, 1);
}

// round 8
// speedup vs baseline: 2.2094x; 1.1441x over previous
#include <cuda_runtime.h>
#include <stdint.h>
#include <math.h>

// ---------------- problem constants ----------------
#define BATCH  2
#define SEQ    2048
#define DMODEL 2048
#define NHEAD  16
#define HDIM   128
#define FDIM   5504
#define MTOK   (BATCH*SEQ)      // 4096 token rows

// ---------------- device scratch ----------------
__device__ float g_xn  [MTOK*DMODEL];
__device__ float g_q   [MTOK*DMODEL];
__device__ float g_k   [MTOK*DMODEL];
__device__ float g_v   [MTOK*DMODEL];
__device__ float g_ctx [MTOK*DMODEL];
__device__ float g_h2  [MTOK*DMODEL];
__device__ float g_actg[MTOK*FDIM];
__device__ float g_actu[MTOK*FDIM];
__device__ float g_mask[MTOK];

// ---------------- common PTX helpers ----------------
__device__ __forceinline__ void cp16(uint32_t dst, const void* src) {
    asm volatile("cp.async.cg.shared.global [%0], [%1], 16;\n" :: "r"(dst), "l"(src));
}
__device__ __forceinline__ uint32_t f2tf32(float x) {
    uint32_t r;
    asm("cvt.rna.tf32.f32 %0, %1;\n" : "=r"(r) : "f"(x));
    return r;
}
__device__ __forceinline__ void mma_tf32(float* c, const uint32_t* a, const uint32_t* b) {
    asm volatile(
        "mma.sync.aligned.m16n8k8.row.col.f32.tf32.tf32.f32 "
        "{%0,%1,%2,%3}, {%4,%5,%6,%7}, {%8,%9}, {%0,%1,%2,%3};\n"
        : "+f"(c[0]), "+f"(c[1]), "+f"(c[2]), "+f"(c[3])
        : "r"(a[0]), "r"(a[1]), "r"(a[2]), "r"(a[3]), "r"(b[0]), "r"(b[1]));
}

// ---------------- RMSNorm ----------------
__global__ __launch_bounds__(256) void rmsnorm_kernel(const float* __restrict__ x,
                                                      const float* __restrict__ w,
                                                      float* __restrict__ o)
{
    int row = blockIdx.x, tid = threadIdx.x;
    const float4* xr = (const float4*)(x + (size_t)row * DMODEL);
    float4 v0 = xr[tid];
    float4 v1 = xr[tid + 256];
    float ss = v0.x*v0.x + v0.y*v0.y + v0.z*v0.z + v0.w*v0.w
             + v1.x*v1.x + v1.y*v1.y + v1.z*v1.z + v1.w*v1.w;
    __shared__ float red[256];
    red[tid] = ss; __syncthreads();
    for (int off = 128; off > 0; off >>= 1) {
        if (tid < off) red[tid] += red[tid + off];
        __syncthreads();
    }
    float r = rsqrtf(red[0] * (1.0f / DMODEL) + 1e-6f);
    const float4* wr = (const float4*)w;
    float4 w0 = wr[tid], w1 = wr[tid + 256];
    float4* orow = (float4*)(o + (size_t)row * DMODEL);
    orow[tid]       = make_float4(v0.x*r*w0.x, v0.y*r*w0.y, v0.z*r*w0.z, v0.w*r*w0.w);
    orow[tid + 256] = make_float4(v1.x*r*w1.x, v1.y*r*w1.y, v1.z*r*w1.z, v1.w*r*w1.w);
}

// ---------------- tf32 tensor-core GEMM: C[M,N] = A[M,K] @ W[N,K]^T ----------------
// mode 0: C = acc + bias[n] (bias may be null)
// mode 1: C = acc + resid[m,n]
// mode 2: C += sel * acc, sel = (expert==0 ? mask[m] : 1-mask[m])
// mode 3: C = acc * silu(resid[m,n])        (fused SwiGLU: resid = gate activations)
#define TBM 128
#define TBN 128
#define TBK 32
#define SST 36                   // smem row stride (floats) -> conflict-free frags
#define STAGE_F (128*SST)        // 4608 floats per stage per operand
#define GEMM_SMEM_BYTES (4*STAGE_F*4)   // 2 operands x 2 stages

__global__ __launch_bounds__(256) void gemm_tf32(const float* __restrict__ A,
                                                 const float* __restrict__ W,
                                                 const float* __restrict__ bias,
                                                 const float* __restrict__ resid,
                                                 const float* __restrict__ mask,
                                                 float* __restrict__ C,
                                                 int M, int N, int K, int mode, int expert)
{
    extern __shared__ float sm[];
    float* As = sm;                    // [2][STAGE_F]
    float* Ws = sm + 2*STAGE_F;        // [2][STAGE_F]

    const int tid = threadIdx.x;
    const int m0 = blockIdx.y * TBM, n0 = blockIdx.x * TBN;

    const int lrow = tid >> 1, lcol = (tid & 1) * 16;
    const float* Ag = A + (size_t)(m0 + lrow) * K + lcol;
    const float* Wg = W + (size_t)(n0 + lrow) * K + lcol;
    uint32_t aBase = (uint32_t)__cvta_generic_to_shared(As + lrow*SST + lcol);
    uint32_t wBase = (uint32_t)__cvta_generic_to_shared(Ws + lrow*SST + lcol);

    const int wid = tid >> 5, lane = tid & 31;
    const int g = lane >> 2, cq = lane & 3;
    const int wm = (wid & 1) * 64;     // warp tile 64x32
    const int wn = (wid >> 1) * 32;

    float acc[4][4][4];
    #pragma unroll
    for (int mt = 0; mt < 4; mt++)
        #pragma unroll
        for (int nt = 0; nt < 4; nt++)
            #pragma unroll
            for (int i = 0; i < 4; i++) acc[mt][nt][i] = 0.f;

    const int ktiles = K / TBK;

    #pragma unroll
    for (int u = 0; u < 4; u++) {
        cp16(aBase + u*16, Ag + u*4);
        cp16(wBase + u*16, Wg + u*4);
    }
    asm volatile("cp.async.commit_group;\n");

    int buf = 0;
    for (int kt = 0; kt < ktiles; kt++) {
        if (kt + 1 < ktiles) {
            const float* ag = Ag + (size_t)(kt+1) * TBK;
            const float* wg = Wg + (size_t)(kt+1) * TBK;
            uint32_t ab = aBase + (uint32_t)(buf^1) * STAGE_F * 4;
            uint32_t wb = wBase + (uint32_t)(buf^1) * STAGE_F * 4;
            #pragma unroll
            for (int u = 0; u < 4; u++) {
                cp16(ab + u*16, ag + u*4);
                cp16(wb + u*16, wg + u*4);
            }
        }
        asm volatile("cp.async.commit_group;\n");
        asm volatile("cp.async.wait_group 1;\n");
        __syncthreads();

        const float* Ab = As + buf*STAGE_F;
        const float* Wb = Ws + buf*STAGE_F;
        #pragma unroll
        for (int ks = 0; ks < 4; ks++) {
            const int kk = ks * 8;
            uint32_t a[4][4], b[4][2];
            #pragma unroll
            for (int mt = 0; mt < 4; mt++) {
                const float* p = Ab + (wm + mt*16 + g)*SST + kk + cq;
                a[mt][0] = f2tf32(p[0]);
                a[mt][1] = f2tf32(p[8*SST]);
                a[mt][2] = f2tf32(p[4]);
                a[mt][3] = f2tf32(p[8*SST + 4]);
            }
            #pragma unroll
            for (int nt = 0; nt < 4; nt++) {
                const float* p = Wb + (wn + nt*8 + g)*SST + kk + cq;
                b[nt][0] = f2tf32(p[0]);
                b[nt][1] = f2tf32(p[4]);
            }
            #pragma unroll
            for (int mt = 0; mt < 4; mt++)
                #pragma unroll
                for (int nt = 0; nt < 4; nt++)
                    mma_tf32(acc[mt][nt], a[mt], b[nt]);
        }
        __syncthreads();
        buf ^= 1;
    }

    // epilogue
    #pragma unroll
    for (int mt = 0; mt < 4; mt++) {
        const int r0 = m0 + wm + mt*16 + g;
        #pragma unroll
        for (int nt = 0; nt < 4; nt++) {
            const int cc = n0 + wn + nt*8 + cq*2;
            const float* c = acc[mt][nt];
            size_t i0 = (size_t)r0 * N + cc;
            size_t i1 = (size_t)(r0 + 8) * N + cc;
            if (mode == 0) {
                float b0 = bias ? bias[cc] : 0.f;
                float b1 = bias ? bias[cc+1] : 0.f;
                C[i0] = c[0] + b0;  C[i0+1] = c[1] + b1;
                C[i1] = c[2] + b0;  C[i1+1] = c[3] + b1;
            } else if (mode == 1) {
                C[i0] = c[0] + resid[i0];  C[i0+1] = c[1] + resid[i0+1];
                C[i1] = c[2] + resid[i1];  C[i1+1] = c[3] + resid[i1+1];
            } else if (mode == 2) {
                float s0 = (expert == 0) ? mask[r0]   : (1.f - mask[r0]);
                float s1 = (expert == 0) ? mask[r0+8] : (1.f - mask[r0+8]);
                C[i0] += s0*c[0];  C[i0+1] += s0*c[1];
                C[i1] += s1*c[2];  C[i1+1] += s1*c[3];
            } else {
                float g0 = resid[i0], g1 = resid[i0+1];
                float g2 = resid[i1], g3 = resid[i1+1];
                C[i0]   = c[0] * (g0 / (1.f + __expf(-g0)));
                C[i0+1] = c[1] * (g1 / (1.f + __expf(-g1)));
                C[i1]   = c[2] * (g2 / (1.f + __expf(-g2)));
                C[i1+1] = c[3] * (g3 / (1.f + __expf(-g3)));
            }
        }
    }
}

// ---------------- RoPE (in-place on q and k) ----------------
__global__ __launch_bounds__(256) void rope_kernel(float* __restrict__ q, float* __restrict__ k)
{
    int t = blockIdx.x * 256 + threadIdx.x;
    int d = t & 63;
    int h = (t >> 6) & (NHEAD - 1);
    int row = t >> 10;
    float pos = (float)(row & (SEQ - 1));
    float invf = __powf(10000.f, -(float)d * (1.f / 64.f));
    float fr = pos * invf;
    float sn, cs;
    sincosf(fr, &sn, &cs);
    size_t base = (size_t)row * DMODEL + h * HDIM + d;
    float qlo = q[base], qhi = q[base + 64];
    q[base]      = qlo * cs - qhi * sn;
    q[base + 64] = qhi * cs + qlo * sn;
    float klo = k[base], khi = k[base + 64];
    k[base]      = klo * cs - khi * sn;
    k[base + 64] = khi * cs + klo * sn;
}

// ---------------- tensor-core flash attention (tf32) ----------------
// 64 q-rows per CTA, 64-key tiles. 8 warps.
// S phase: warp (wr=wid&3, wc=wid>>2) computes S[16*wr..+16][32*wc..+32].
// PV phase computed as O^T = V^T @ P^T: warp wid owns dims [16*wid..+16), all 64 q.
#define AQS 132   // Q/K smem stride (132 % 32 == 4 -> frag LDS conflict-free)
#define AVS 136   // V smem stride   (136 % 32 == 8 -> frag LDS conflict-free)
#define APS 68    // P smem stride   ( 68 % 32 == 4 -> frag LDS conflict-free)
#define ATT_Q  0
#define ATT_K  (64*AQS)
#define ATT_V  (ATT_K + 64*AQS)
#define ATT_P  (ATT_V + 64*AVS)
#define ATT_M  (ATT_P + 64*APS)
#define ATT_L  (ATT_M + 64)
#define ATT_AL (ATT_L + 64)
#define ATT_MH (ATT_AL + 64)
#define ATT_SH (ATT_MH + 128)
#define ATT_TOT (ATT_SH + 128)
#define ATT_BYTES (ATT_TOT*4)

__global__ __launch_bounds__(256) void attn_tc(const float* __restrict__ q,
                                               const float* __restrict__ k,
                                               const float* __restrict__ v,
                                               float* __restrict__ o)
{
    extern __shared__ float sm[];
    uint32_t* Qs = (uint32_t*)(sm + ATT_Q);
    uint32_t* Ks = (uint32_t*)(sm + ATT_K);
    uint32_t* Vs = (uint32_t*)(sm + ATT_V);
    uint32_t* Ps = (uint32_t*)(sm + ATT_P);

    const int tid = threadIdx.x;
    const int wid = tid >> 5, lane = tid & 31;
    const int wr = wid & 3, wc = wid >> 2;
    const int g = lane >> 2, cq = lane & 3;
    const int qt = gridDim.x - 1 - blockIdx.x;   // long blocks first
    const int h = blockIdx.y, b = blockIdx.z;
    const int qbase = qt * 64;
    const int frow = tid >> 2, fdg = (tid & 3) * 4;
    const float qscale = 0.08838834764831845f;   // 1/sqrt(128)

    { // fill Q (tf32, pre-scaled)
        const float* src = q + (size_t)(b*SEQ + qbase + frow) * DMODEL + h*HDIM;
        #pragma unroll
        for (int u = 0; u < 8; u++) {
            int d = fdg + 16*u;
            float4 t = *(const float4*)(src + d);
            uint4 pk;
            pk.x = f2tf32(t.x*qscale); pk.y = f2tf32(t.y*qscale);
            pk.z = f2tf32(t.z*qscale); pk.w = f2tf32(t.w*qscale);
            *(uint4*)(Qs + frow*AQS + d) = pk;
        }
    }
    if (tid < 64) { sm[ATT_M + tid] = -1e30f; sm[ATT_L + tid] = 0.f; }

    float oacc[8][4];
    #pragma unroll
    for (int nt = 0; nt < 8; nt++)
        #pragma unroll
        for (int j = 0; j < 4; j++) oacc[nt][j] = 0.f;

    const int r0 = 16*wr + g, r1 = r0 + 8;

    for (int kt = 0; kt <= qt; kt++) {
        __syncthreads();   // previous iter done reading Ks/Vs
        { // fill K and V tiles (tf32)
            const float* ksrc = k + (size_t)(b*SEQ + kt*64 + frow) * DMODEL + h*HDIM;
            const float* vsrc = v + (size_t)(b*SEQ + kt*64 + frow) * DMODEL + h*HDIM;
            #pragma unroll
            for (int u = 0; u < 8; u++) {
                int d = fdg + 16*u;
                float4 t = *(const float4*)(ksrc + d);
                uint4 pk;
                pk.x = f2tf32(t.x); pk.y = f2tf32(t.y);
                pk.z = f2tf32(t.z); pk.w = f2tf32(t.w);
                *(uint4*)(Ks + frow*AQS + d) = pk;
                float4 tv = *(const float4*)(vsrc + d);
                uint4 pv;
                pv.x = f2tf32(tv.x); pv.y = f2tf32(tv.y);
                pv.z = f2tf32(tv.z); pv.w = f2tf32(tv.w);
                *(uint4*)(Vs + frow*AVS + d) = pv;
            }
        }
        __syncthreads();

        // ---- S = Q K^T over warp's 16x32 tile ----
        float s[4][4];
        #pragma unroll
        for (int nt = 0; nt < 4; nt++)
            #pragma unroll
            for (int j = 0; j < 4; j++) s[nt][j] = 0.f;

        #pragma unroll
        for (int ks = 0; ks < 16; ks++) {
            uint32_t a[4];
            const uint32_t* qp = Qs + r0*AQS + 8*ks + cq;
            a[0] = qp[0];
            a[1] = qp[8*AQS];
            a[2] = qp[4];
            a[3] = qp[8*AQS + 4];
            #pragma unroll
            for (int nt = 0; nt < 4; nt++) {
                const uint32_t* kp = Ks + (32*wc + 8*nt + g)*AQS + 8*ks + cq;
                uint32_t bb[2] = {kp[0], kp[4]};
                mma_tf32(s[nt], a, bb);
            }
        }

        if (kt == qt) { // causal mask (diagonal tile only)
            #pragma unroll
            for (int nt = 0; nt < 4; nt++) {
                int c0 = 32*wc + 8*nt + 2*cq;
                if (c0   > r0) s[nt][0] = -1e30f;
                if (c0+1 > r0) s[nt][1] = -1e30f;
                if (c0   > r1) s[nt][2] = -1e30f;
                if (c0+1 > r1) s[nt][3] = -1e30f;
            }
        }

        // ---- online softmax ----
        float m0 = -1e30f, m1 = -1e30f;
        #pragma unroll
        for (int nt = 0; nt < 4; nt++) {
            m0 = fmaxf(m0, fmaxf(s[nt][0], s[nt][1]));
            m1 = fmaxf(m1, fmaxf(s[nt][2], s[nt][3]));
        }
        m0 = fmaxf(m0, __shfl_xor_sync(0xffffffffu, m0, 1));
        m0 = fmaxf(m0, __shfl_xor_sync(0xffffffffu, m0, 2));
        m1 = fmaxf(m1, __shfl_xor_sync(0xffffffffu, m1, 1));
        m1 = fmaxf(m1, __shfl_xor_sync(0xffffffffu, m1, 2));
        if (cq == 0) {
            sm[ATT_MH + wc*64 + r0] = m0;
            sm[ATT_MH + wc*64 + r1] = m1;
        }
        __syncthreads();

        float mo0 = sm[ATT_M + r0], mo1 = sm[ATT_M + r1];
        float mn0 = fmaxf(mo0, fmaxf(sm[ATT_MH + r0], sm[ATT_MH + 64 + r0]));
        float mn1 = fmaxf(mo1, fmaxf(sm[ATT_MH + r1], sm[ATT_MH + 64 + r1]));
        float sum0 = 0.f, sum1 = 0.f;
        #pragma unroll
        for (int nt = 0; nt < 4; nt++) {
            float p0 = __expf(s[nt][0] - mn0);
            float p1 = __expf(s[nt][1] - mn0);
            float p2 = __expf(s[nt][2] - mn1);
            float p3 = __expf(s[nt][3] - mn1);
            sum0 += p0 + p1;  sum1 += p2 + p3;
            int cc = 32*wc + 8*nt + 2*cq;
            uint32_t* pp0 = Ps + r0*APS + cc;
            pp0[0] = f2tf32(p0);  pp0[1] = f2tf32(p1);
            uint32_t* pp1 = Ps + r1*APS + cc;
            pp1[0] = f2tf32(p2);  pp1[1] = f2tf32(p3);
        }
        sum0 += __shfl_xor_sync(0xffffffffu, sum0, 1);
        sum0 += __shfl_xor_sync(0xffffffffu, sum0, 2);
        sum1 += __shfl_xor_sync(0xffffffffu, sum1, 1);
        sum1 += __shfl_xor_sync(0xffffffffu, sum1, 2);
        if (cq == 0) {
            sm[ATT_SH + wc*64 + r0] = sum0;
            sm[ATT_SH + wc*64 + r1] = sum1;
            if (wc == 0) {
                sm[ATT_AL + r0] = __expf(mo0 - mn0);
                sm[ATT_AL + r1] = __expf(mo1 - mn1);
            }
        }
        __syncthreads();

        if (tid < 64) {
            int r = tid;
            float mo = sm[ATT_M + r];
            float mn = fmaxf(mo, fmaxf(sm[ATT_MH + r], sm[ATT_MH + 64 + r]));
            sm[ATT_L + r] = sm[ATT_L + r] * sm[ATT_AL + r]
                          + sm[ATT_SH + r] + sm[ATT_SH + 64 + r];
            sm[ATT_M + r] = mn;
        }

        // ---- rescale O accumulators (alpha indexed by q column) ----
        #pragma unroll
        for (int nt = 0; nt < 8; nt++) {
            float a0 = sm[ATT_AL + 8*nt + 2*cq];
            float a1 = sm[ATT_AL + 8*nt + 2*cq + 1];
            oacc[nt][0] *= a0;  oacc[nt][1] *= a1;
            oacc[nt][2] *= a0;  oacc[nt][3] *= a1;
        }

        // ---- O^T += V^T P^T : warp owns dims [16*wid .. +16) ----
        #pragma unroll
        for (int ks = 0; ks < 8; ks++) {
            uint32_t a[4];
            const uint32_t* vp = Vs + (8*ks + cq)*AVS + 16*wid + g;
            a[0] = vp[0];
            a[1] = vp[8];
            a[2] = vp[4*AVS];
            a[3] = vp[4*AVS + 8];
            #pragma unroll
            for (int nt = 0; nt < 8; nt++) {
                const uint32_t* pp = Ps + (8*nt + g)*APS + 8*ks + cq;
                uint32_t bb[2] = {pp[0], pp[4]};
                mma_tf32(oacc[nt], a, bb);
            }
        }
    }

    __syncthreads();
    // ---- epilogue: O[q][d] = O^T[d][q] / L[q] ----
    #pragma unroll
    for (int nt = 0; nt < 8; nt++) {
        int q0 = qbase + 8*nt + 2*cq;
        float l0 = 1.f / sm[ATT_L + 8*nt + 2*cq];
        float l1 = 1.f / sm[ATT_L + 8*nt + 2*cq + 1];
        int d0 = 16*wid + g;
        float* ob  = o + (size_t)(b*SEQ + q0) * DMODEL + h*HDIM + d0;
        float* ob1 = ob + DMODEL;
        ob [0] = oacc[nt][0] * l0;
        ob [8] = oacc[nt][2] * l0;
        ob1[0] = oacc[nt][1] * l1;
        ob1[8] = oacc[nt][3] * l1;
    }
}

// ---------------- router ----------------
__global__ __launch_bounds__(128) void router_kernel(const float* __restrict__ xn,
                                                     const float* __restrict__ rw,
                                                     const float* __restrict__ rb,
                                                     float* __restrict__ mask)
{
    int row = blockIdx.x, tid = threadIdx.x;
    float a0 = 0.f, a1 = 0.f;
    const float* xr = xn + (size_t)row * DMODEL;
    for (int d = tid; d < DMODEL; d += 128) {
        float x = xr[d];
        a0 += x * rw[d];
        a1 += x * rw[DMODEL + d];
    }
    __shared__ float s0[128], s1[128];
    s0[tid] = a0; s1[tid] = a1; __syncthreads();
    for (int off = 64; off > 0; off >>= 1) {
        if (tid < off) { s0[tid] += s0[tid + off]; s1[tid] += s1[tid + off]; }
        __syncthreads();
    }
    if (tid == 0)
        mask[row] = (s0[0] + rb[0] >= s1[0] + rb[1]) ? 1.f : 0.f;
}

// ---------------- launch ----------------
extern "C" void kernel_launch(void* const* d_in, const int* in_sizes, int n_in,
                              void* d_out, int out_size)
{
    const float* hidden = (const float*)d_in[0];
    const float* ln1w   = (const float*)d_in[1];
    const float* wq     = (const float*)d_in[2];
    const float* bq     = (const float*)d_in[3];
    const float* wk     = (const float*)d_in[4];
    const float* bk     = (const float*)d_in[5];
    const float* wv     = (const float*)d_in[6];
    const float* bv     = (const float*)d_in[7];
    const float* wo     = (const float*)d_in[8];
    const float* ln2w   = (const float*)d_in[9];
    const float* e1g    = (const float*)d_in[10];
    const float* e1u    = (const float*)d_in[11];
    const float* e1d    = (const float*)d_in[12];
    const float* e2g    = (const float*)d_in[13];
    const float* e2u    = (const float*)d_in[14];
    const float* e2d    = (const float*)d_in[15];
    const float* rw     = (const float*)d_in[16];
    const float* rb     = (const float*)d_in[17];
    float* out = (float*)d_out;

    void* p;
    cudaGetSymbolAddress(&p, g_xn);   float* xn   = (float*)p;
    cudaGetSymbolAddress(&p, g_q);    float* q    = (float*)p;
    cudaGetSymbolAddress(&p, g_k);    float* k    = (float*)p;
    cudaGetSymbolAddress(&p, g_v);    float* v    = (float*)p;
    cudaGetSymbolAddress(&p, g_ctx);  float* ctx  = (float*)p;
    cudaGetSymbolAddress(&p, g_h2);   float* h2   = (float*)p;
    cudaGetSymbolAddress(&p, g_actg); float* actg = (float*)p;
    cudaGetSymbolAddress(&p, g_actu); float* actu = (float*)p;
    cudaGetSymbolAddress(&p, g_mask); float* mask = (float*)p;

    cudaFuncSetAttribute(gemm_tf32, cudaFuncAttributeMaxDynamicSharedMemorySize, GEMM_SMEM_BYTES);
    cudaFuncSetAttribute(attn_tc,   cudaFuncAttributeMaxDynamicSharedMemorySize, ATT_BYTES);

    // 1. pre-attention norm
    rmsnorm_kernel<<<MTOK, 256>>>(hidden, ln1w, xn);

    // 2. QKV projections
    dim3 gD(DMODEL/TBN, MTOK/TBM);
    gemm_tf32<<<gD, 256, GEMM_SMEM_BYTES>>>(xn, wq, bq, nullptr, nullptr, q, MTOK, DMODEL, DMODEL, 0, 0);
    gemm_tf32<<<gD, 256, GEMM_SMEM_BYTES>>>(xn, wk, bk, nullptr, nullptr, k, MTOK, DMODEL, DMODEL, 0, 0);
    gemm_tf32<<<gD, 256, GEMM_SMEM_BYTES>>>(xn, wv, bv, nullptr, nullptr, v, MTOK, DMODEL, DMODEL, 0, 0);

    // 3. RoPE
    rope_kernel<<<(MTOK*NHEAD*64)/256, 256>>>(q, k);

    // 4. tensor-core causal attention
    attn_tc<<<dim3(SEQ/64, NHEAD, BATCH), 256, ATT_BYTES>>>(q, k, v, ctx);

    // 5. O projection + residual
    gemm_tf32<<<gD, 256, GEMM_SMEM_BYTES>>>(ctx, wo, nullptr, hidden, nullptr, h2, MTOK, DMODEL, DMODEL, 1, 0);

    // 6. post-attention norm + router
    rmsnorm_kernel<<<MTOK, 256>>>(h2, ln2w, xn);
    router_kernel<<<MTOK, 128>>>(xn, rw, rb, mask);

    // 7. residual into output
    cudaMemcpyAsync(out, h2, (size_t)MTOK * DMODEL * sizeof(float),
                    cudaMemcpyDeviceToDevice, 0);

    // 8. expert 1 (SiLU fused into up-GEMM epilogue, mode 3)
    dim3 gF(FDIM/TBN, MTOK/TBM);
    gemm_tf32<<<gF, 256, GEMM_SMEM_BYTES>>>(xn, e1g, nullptr, nullptr, nullptr, actg, MTOK, FDIM, DMODEL, 0, 0);
    gemm_tf32<<<gF, 256, GEMM_SMEM_BYTES>>>(xn, e1u, nullptr, actg, nullptr, actu, MTOK, FDIM, DMODEL, 3, 0);
    gemm_tf32<<<gD, 256, GEMM_SMEM_BYTES>>>(actu, e1d, nullptr, nullptr, mask, out, MTOK, DMODEL, FDIM, 2, 0);

    // 9. expert 2
    gemm_tf32<<<gF, 256, GEMM_SMEM_BYTES>>>(xn, e2g, nullptr, nullptr, nullptr, actg, MTOK, FDIM, DMODEL, 0, 0);
    gemm_tf32<<<gF, 256, GEMM_SMEM_BYTES>>>(xn, e2u, nullptr, actg, nullptr, actu, MTOK, FDIM, DMODEL, 3, 0);
    gemm_tf32<<<gD, 256, GEMM_SMEM_BYTES>>>(actu, e2d, nullptr, nullptr, mask, out, MTOK, DMODEL, FDIM, 2, 1);
}